// round 2
// baseline (speedup 1.0000x reference)
#include <cuda_runtime.h>
#include <math.h>

#define D_MODEL 768
#define SEQ     4096
#define NH      12
#define DK      64
#define RANK    8
#define LORA_SCALE 2.0f      // alpha/rank = 16/8
#define ATT_SCALE  0.125f    // 1/sqrt(64)

// ---------------- scratch (device globals: no allocation allowed) ------------
__device__ float g_wq[D_MODEL * D_MODEL];
__device__ float g_wk[D_MODEL * D_MODEL];
__device__ float g_wv[D_MODEL * D_MODEL];
__device__ float g_q[SEQ * D_MODEL];
__device__ float g_k[SEQ * D_MODEL];
__device__ float g_v[SEQ * D_MODEL];
__device__ float g_attn[SEQ * D_MODEL];

// ---------------- fold LoRA into base weight: W_eff = W + 2 * up @ down ------
__global__ void fold_kernel(const float* __restrict__ w,
                            const float* __restrict__ up,
                            const float* __restrict__ dn,
                            float* __restrict__ out) {
    int idx = blockIdx.x * 256 + threadIdx.x;
    if (idx >= D_MODEL * D_MODEL) return;
    int e = idx / D_MODEL, d = idx % D_MODEL;
    float acc = w[idx];
#pragma unroll
    for (int r = 0; r < RANK; r++)
        acc += LORA_SCALE * up[e * RANK + r] * dn[r * D_MODEL + d];
    out[idx] = acc;
}

// ---------------- NT GEMM: Y[M,N] = X[M,K] @ W[N,K]^T + bias -----------------
// BM=BN=64, BK=16, 256 threads, 4x4 microtile. Smem stored k-major so inner
// loop reads are LDS.128 (2 per 16 FMA).
__global__ void __launch_bounds__(256) gemm_nt_bias(
    const float* __restrict__ X, const float* __restrict__ W,
    const float* __restrict__ bias, float* __restrict__ Y,
    int M, int N, int K)
{
    __shared__ float Xs[16][68];
    __shared__ float Ws[16][68];
    int tid = threadIdx.x;
    int ty = tid >> 4, tx = tid & 15;
    int m0 = blockIdx.x * 64, n0 = blockIdx.y * 64;
    float acc[4][4] = {};

    for (int k0 = 0; k0 < K; k0 += 16) {
#pragma unroll
        for (int t = 0; t < 4; t++) {
            int i = tid + t * 256;           // 1024 elements per tile
            int mr = i >> 4, kk = i & 15;
            Xs[kk][mr] = X[(m0 + mr) * K + k0 + kk];
            Ws[kk][mr] = W[(n0 + mr) * K + k0 + kk];
        }
        __syncthreads();
#pragma unroll
        for (int kk = 0; kk < 16; kk++) {
            float4 a = *(const float4*)&Xs[kk][ty * 4];
            float4 b = *(const float4*)&Ws[kk][tx * 4];
            float av[4] = {a.x, a.y, a.z, a.w};
            float bv[4] = {b.x, b.y, b.z, b.w};
#pragma unroll
            for (int i = 0; i < 4; i++)
#pragma unroll
                for (int j = 0; j < 4; j++)
                    acc[i][j] += av[i] * bv[j];
        }
        __syncthreads();
    }
#pragma unroll
    for (int i = 0; i < 4; i++) {
        int m = m0 + ty * 4 + i;
#pragma unroll
        for (int j = 0; j < 4; j++) {
            int n = n0 + tx * 4 + j;
            Y[m * N + n] = acc[i][j] + bias[n];
        }
    }
}

// ---------------- flash attention, fp32, 64x64 tiles -------------------------
// grid: (SEQ/64, NH), 256 threads. Q tile resident; stream K/V tiles with
// online softmax. S written to smem; P written transposed so PV inner loop is
// also pure LDS.128.
#define SROW 68
#define ATT_SMEM_FLOATS (5 * 64 * SROW + 3 * 64)

__global__ void __launch_bounds__(256) flash_attn_kernel()
{
    extern __shared__ float smem[];
    float* Qs = smem;                  // [d][r]
    float* Ks = Qs + 64 * SROW;        // [d][c]
    float* Vs = Ks + 64 * SROW;        // [k][dd]
    float* Ss = Vs + 64 * SROW;        // [r][c]
    float* Pt = Ss + 64 * SROW;        // [c][r]
    float* row_max   = Pt + 64 * SROW;
    float* row_sum   = row_max + 64;
    float* row_alpha = row_sum + 64;

    int tid = threadIdx.x;
    int ty = tid >> 4, tx = tid & 15;
    int qt = blockIdx.x, h = blockIdx.y;
    const float* Qg = g_q + h * DK;
    const float* Kg = g_k + h * DK;
    const float* Vg = g_v + h * DK;

    // Q tile, transposed into smem: Qs[d][r]
#pragma unroll
    for (int t = 0; t < 16; t++) {
        int i = tid + t * 256;
        int r = i >> 6, d = i & 63;
        Qs[d * SROW + r] = Qg[(qt * 64 + r) * D_MODEL + d];
    }
    if (tid < 64) { row_max[tid] = -1e30f; row_sum[tid] = 0.0f; }

    float O[4][4] = {};

    for (int kt = 0; kt < SEQ / 64; kt++) {
        __syncthreads();   // prior iter's Pt/Vs reads done; Q/row-state visible
#pragma unroll
        for (int t = 0; t < 16; t++) {
            int i = tid + t * 256;
            int r = i >> 6, d = i & 63;
            Ks[d * SROW + r] = Kg[(kt * 64 + r) * D_MODEL + d];
            Vs[r * SROW + d] = Vg[(kt * 64 + r) * D_MODEL + d];
        }
        __syncthreads();

        // S = (Q K^T) * scale
        float sacc[4][4] = {};
#pragma unroll
        for (int d = 0; d < 64; d++) {
            float4 a = *(const float4*)&Qs[d * SROW + ty * 4];
            float4 b = *(const float4*)&Ks[d * SROW + tx * 4];
            float av[4] = {a.x, a.y, a.z, a.w};
            float bv[4] = {b.x, b.y, b.z, b.w};
#pragma unroll
            for (int i = 0; i < 4; i++)
#pragma unroll
                for (int j = 0; j < 4; j++)
                    sacc[i][j] += av[i] * bv[j];
        }
#pragma unroll
        for (int i = 0; i < 4; i++) {
            float4 sv;
            sv.x = sacc[i][0] * ATT_SCALE;
            sv.y = sacc[i][1] * ATT_SCALE;
            sv.z = sacc[i][2] * ATT_SCALE;
            sv.w = sacc[i][3] * ATT_SCALE;
            *(float4*)&Ss[(ty * 4 + i) * SROW + tx * 4] = sv;
        }
        __syncthreads();

        // online softmax: 4 lanes per row (same warp -> shfl group of 4)
        {
            int row = tid >> 2;
            int l4  = tid & 3;
            const float* srow = Ss + row * SROW + l4 * 16;
            float m = -1e30f;
#pragma unroll
            for (int c = 0; c < 16; c++) m = fmaxf(m, srow[c]);
            m = fmaxf(m, __shfl_xor_sync(0xffffffffu, m, 1));
            m = fmaxf(m, __shfl_xor_sync(0xffffffffu, m, 2));
            float om = row_max[row];
            float nm = fmaxf(om, m);
            float alpha = __expf(om - nm);
            float lsum = 0.0f;
#pragma unroll
            for (int c = 0; c < 16; c++) {
                float p = __expf(srow[c] - nm);
                lsum += p;
                Pt[(l4 * 16 + c) * SROW + row] = p;
            }
            lsum += __shfl_xor_sync(0xffffffffu, lsum, 1);
            lsum += __shfl_xor_sync(0xffffffffu, lsum, 2);
            if (l4 == 0) {
                row_sum[row] = row_sum[row] * alpha + lsum;
                row_max[row] = nm;
                row_alpha[row] = alpha;
            }
        }
        __syncthreads();

        // rescale O, then O += P @ V
#pragma unroll
        for (int i = 0; i < 4; i++) {
            float al = row_alpha[ty * 4 + i];
#pragma unroll
            for (int j = 0; j < 4; j++) O[i][j] *= al;
        }
#pragma unroll
        for (int k = 0; k < 64; k++) {
            float4 a = *(const float4*)&Pt[k * SROW + ty * 4];
            float4 b = *(const float4*)&Vs[k * SROW + tx * 4];
            float av[4] = {a.x, a.y, a.z, a.w};
            float bv[4] = {b.x, b.y, b.z, b.w};
#pragma unroll
            for (int i = 0; i < 4; i++)
#pragma unroll
                for (int j = 0; j < 4; j++)
                    O[i][j] += av[i] * bv[j];
        }
    }

    // final normalize + write (row_sum last written before the final in-loop sync)
#pragma unroll
    for (int i = 0; i < 4; i++) {
        int r = qt * 64 + ty * 4 + i;
        float inv = 1.0f / row_sum[ty * 4 + i];
        float4 o;
        o.x = O[i][0] * inv; o.y = O[i][1] * inv;
        o.z = O[i][2] * inv; o.w = O[i][3] * inv;
        *(float4*)&g_attn[r * D_MODEL + h * DK + tx * 4] = o;
    }
}

// ---------------- launch -----------------------------------------------------
extern "C" void kernel_launch(void* const* d_in, const int* in_sizes, int n_in,
                              void* d_out, int out_size) {
    (void)in_sizes; (void)n_in; (void)out_size;
    const float* x       = (const float*)d_in[0];
    const float* wq      = (const float*)d_in[1];
    const float* bq      = (const float*)d_in[2];
    const float* wk      = (const float*)d_in[3];
    const float* bk      = (const float*)d_in[4];
    const float* wv      = (const float*)d_in[5];
    const float* bv      = (const float*)d_in[6];
    const float* wo      = (const float*)d_in[7];
    const float* bo      = (const float*)d_in[8];
    const float* wq_down = (const float*)d_in[9];
    const float* wq_up   = (const float*)d_in[10];
    const float* wk_down = (const float*)d_in[11];
    const float* wk_up   = (const float*)d_in[12];
    const float* wv_down = (const float*)d_in[13];
    const float* wv_up   = (const float*)d_in[14];
    float* out = (float*)d_out;

    float *p_wq, *p_wk, *p_wv, *p_q, *p_k, *p_v, *p_attn;
    cudaGetSymbolAddress((void**)&p_wq, g_wq);
    cudaGetSymbolAddress((void**)&p_wk, g_wk);
    cudaGetSymbolAddress((void**)&p_wv, g_wv);
    cudaGetSymbolAddress((void**)&p_q,  g_q);
    cudaGetSymbolAddress((void**)&p_k,  g_k);
    cudaGetSymbolAddress((void**)&p_v,  g_v);
    cudaGetSymbolAddress((void**)&p_attn, g_attn);

    int smem_att = ATT_SMEM_FLOATS * (int)sizeof(float);
    cudaFuncSetAttribute(flash_attn_kernel,
                         cudaFuncAttributeMaxDynamicSharedMemorySize, smem_att);

    int fold_blocks = (D_MODEL * D_MODEL + 255) / 256;
    fold_kernel<<<fold_blocks, 256>>>(wq, wq_up, wq_down, p_wq);
    fold_kernel<<<fold_blocks, 256>>>(wk, wk_up, wk_down, p_wk);
    fold_kernel<<<fold_blocks, 256>>>(wv, wv_up, wv_down, p_wv);

    dim3 ggrid(SEQ / 64, D_MODEL / 64);
    gemm_nt_bias<<<ggrid, 256>>>(x, p_wq, bq, p_q, SEQ, D_MODEL, D_MODEL);
    gemm_nt_bias<<<ggrid, 256>>>(x, p_wk, bk, p_k, SEQ, D_MODEL, D_MODEL);
    gemm_nt_bias<<<ggrid, 256>>>(x, p_wv, bv, p_v, SEQ, D_MODEL, D_MODEL);

    dim3 agrid(SEQ / 64, NH);
    flash_attn_kernel<<<agrid, 256, smem_att>>>();

    gemm_nt_bias<<<ggrid, 256>>>(p_attn, wo, bo, out, SEQ, D_MODEL, D_MODEL);
}

// round 3
// speedup vs baseline: 1.2813x; 1.2813x over previous
#include <cuda_runtime.h>
#include <math.h>

#define D_MODEL 768
#define SEQ     4096
#define NH      12
#define DK      64
#define RANK    8
#define LORA_SCALE 2.0f
#define ATT_SCALE  0.125f
#define NSPLIT  3

// ---------------- scratch (device globals: no allocation allowed) ------------
__device__ float g_wq[D_MODEL * D_MODEL];
__device__ float g_wk[D_MODEL * D_MODEL];
__device__ float g_wv[D_MODEL * D_MODEL];
__device__ float g_q[SEQ * D_MODEL];
__device__ float g_k[SEQ * D_MODEL];
__device__ float g_v[SEQ * D_MODEL];
__device__ float g_attn[SEQ * D_MODEL];
__device__ float g_opart[NSPLIT * SEQ * D_MODEL];          // unnormalized partial O
__device__ float g_ml[2 * NSPLIT * NH * SEQ];              // m then l

// ---------------- fold LoRA into base weight: W_eff = W + 2 * up @ down ------
__global__ void fold_kernel(const float* __restrict__ w,
                            const float* __restrict__ up,
                            const float* __restrict__ dn,
                            float* __restrict__ out) {
    int idx = blockIdx.x * 256 + threadIdx.x;
    if (idx >= D_MODEL * D_MODEL) return;
    int e = idx / D_MODEL, d = idx % D_MODEL;
    float acc = w[idx];
#pragma unroll
    for (int r = 0; r < RANK; r++)
        acc += LORA_SCALE * up[e * RANK + r] * dn[r * D_MODEL + d];
    out[idx] = acc;
}

// ---------------- NT GEMM tile body: Y[M,768] = X[M,768] @ W[768,768]^T + b --
// BM=BN=128, BK=16, 256 threads, 8x8 microtile, double-buffered smem.
// 1 B/FMA smem traffic (crossbar break-even).
__device__ __forceinline__ void gemm_tile(const float* __restrict__ X,
                                          const float* __restrict__ W,
                                          const float* __restrict__ bias,
                                          float* __restrict__ Y)
{
    __shared__ float Xs[2][16][132];
    __shared__ float Ws[2][16][132];
    const int K = D_MODEL, N = D_MODEL;
    int tid = threadIdx.x;
    int tx = tid & 15, ty = tid >> 4;
    int m0 = blockIdx.x * 128, n0 = blockIdx.y * 128;
    int lm = tid & 127;              // loader row
    int lk4 = tid >> 7;              // 0 or 1

    const float* Xp = X + (size_t)(m0 + lm) * K;
    const float* Wp = W + (size_t)(n0 + lm) * K;

    float acc[8][8] = {};

    // prologue: tile 0 -> buf 0
#pragma unroll
    for (int t = 0; t < 2; t++) {
        int k4 = lk4 + t * 2;
        float4 xv = *(const float4*)(Xp + k4 * 4);
        float4 wv = *(const float4*)(Wp + k4 * 4);
        Xs[0][k4*4+0][lm] = xv.x; Xs[0][k4*4+1][lm] = xv.y;
        Xs[0][k4*4+2][lm] = xv.z; Xs[0][k4*4+3][lm] = xv.w;
        Ws[0][k4*4+0][lm] = wv.x; Ws[0][k4*4+1][lm] = wv.y;
        Ws[0][k4*4+2][lm] = wv.z; Ws[0][k4*4+3][lm] = wv.w;
    }
    __syncthreads();

    const int NIT = K / 16;          // 48
    float4 xr[2], wr[2];
    for (int it = 0; it < NIT; it++) {
        int cur = it & 1;
        if (it + 1 < NIT) {
            int k0 = (it + 1) * 16;
#pragma unroll
            for (int t = 0; t < 2; t++) {
                int k4 = lk4 + t * 2;
                xr[t] = *(const float4*)(Xp + k0 + k4 * 4);
                wr[t] = *(const float4*)(Wp + k0 + k4 * 4);
            }
        }
#pragma unroll
        for (int kk = 0; kk < 16; kk++) {
            float4 a0 = *(const float4*)&Xs[cur][kk][ty * 8];
            float4 a1 = *(const float4*)&Xs[cur][kk][ty * 8 + 4];
            float4 b0 = *(const float4*)&Ws[cur][kk][tx * 8];
            float4 b1 = *(const float4*)&Ws[cur][kk][tx * 8 + 4];
            float av[8] = {a0.x,a0.y,a0.z,a0.w,a1.x,a1.y,a1.z,a1.w};
            float bv[8] = {b0.x,b0.y,b0.z,b0.w,b1.x,b1.y,b1.z,b1.w};
#pragma unroll
            for (int i = 0; i < 8; i++)
#pragma unroll
                for (int j = 0; j < 8; j++)
                    acc[i][j] += av[i] * bv[j];
        }
        if (it + 1 < NIT) {
            int nb = cur ^ 1;
#pragma unroll
            for (int t = 0; t < 2; t++) {
                int k4 = lk4 + t * 2;
                Xs[nb][k4*4+0][lm] = xr[t].x; Xs[nb][k4*4+1][lm] = xr[t].y;
                Xs[nb][k4*4+2][lm] = xr[t].z; Xs[nb][k4*4+3][lm] = xr[t].w;
                Ws[nb][k4*4+0][lm] = wr[t].x; Ws[nb][k4*4+1][lm] = wr[t].y;
                Ws[nb][k4*4+2][lm] = wr[t].z; Ws[nb][k4*4+3][lm] = wr[t].w;
            }
        }
        __syncthreads();
    }

    float bv8[8];
#pragma unroll
    for (int j = 0; j < 8; j++) bv8[j] = bias[n0 + tx * 8 + j];
#pragma unroll
    for (int i = 0; i < 8; i++) {
        size_t row = (size_t)(m0 + ty * 8 + i);
        float4 o0 = make_float4(acc[i][0]+bv8[0], acc[i][1]+bv8[1],
                                acc[i][2]+bv8[2], acc[i][3]+bv8[3]);
        float4 o1 = make_float4(acc[i][4]+bv8[4], acc[i][5]+bv8[5],
                                acc[i][6]+bv8[6], acc[i][7]+bv8[7]);
        *(float4*)(Y + row * N + n0 + tx * 8)     = o0;
        *(float4*)(Y + row * N + n0 + tx * 8 + 4) = o1;
    }
}

__global__ void __launch_bounds__(256, 2) gemm_one(
    const float* __restrict__ X, const float* __restrict__ W,
    const float* __restrict__ b, float* __restrict__ Y) {
    gemm_tile(X, W, b, Y);
}

// Q/K/V fused into one grid (z selects) -> 576 CTAs, 1.95 waves @ occ 2.
__global__ void __launch_bounds__(256, 2) gemm_qkv(
    const float* __restrict__ X,
    const float* __restrict__ W0, const float* __restrict__ B0, float* __restrict__ Y0,
    const float* __restrict__ W1, const float* __restrict__ B1, float* __restrict__ Y1,
    const float* __restrict__ W2, const float* __restrict__ B2, float* __restrict__ Y2)
{
    const float* W; const float* B; float* Y;
    if (blockIdx.z == 0)      { W = W0; B = B0; Y = Y0; }
    else if (blockIdx.z == 1) { W = W1; B = B1; Y = Y1; }
    else                      { W = W2; B = B2; Y = Y2; }
    gemm_tile(X, W, B, Y);
}

// ---------------- flash attention: Q-tile 256, K-tile 64, split-K 3 ----------
// 256 threads as 32(ty) x 8(tx). S micro 8x8, O micro 8x8 (both 1 B/FMA).
// Row state (m,l) in registers replicated across the 8-lane tx group.
// P stored transposed with float4 swizzle: phys_r4 = (r4&~7)|((r4&7)^(c>>3))
// -> conflict-free stores AND conflict-free broadcast reads.
#define QPITCH 260
#define KPITCH 68
#define ATT_SMEM_BYTES ((64*QPITCH + 64*KPITCH + 64*KPITCH + 64*QPITCH) * 4)

__global__ void __launch_bounds__(256, 1) flash_attn_split()
{
    extern __shared__ float smem[];
    float* Qs = smem;                       // [64][260]  (d-major)
    float* Ks = smem + 64 * QPITCH;         // [64][68]   (d-major)
    float* Vs = Ks + 64 * KPITCH;           // [64][68]   (k-major, natural)
    float* Pt = Vs + 64 * KPITCH;           // [64][260]  (k-major, swizzled)

    int tid = threadIdx.x;
    int tx = tid & 7, ty = tid >> 3;
    int qt = blockIdx.x, h = blockIdx.y, sp = blockIdx.z;

    const float* Qg = g_q + h * DK;
    const float* Kg = g_k + h * DK;
    const float* Vg = g_v + h * DK;

    // load Q transposed: Qs[d][r], r in [0,256)
#pragma unroll
    for (int t = 0; t < 16; t++) {
        int idx = tid + t * 256;
        int r = idx & 255, d4 = idx >> 8;   // d4: 0..15
        float4 v = *(const float4*)(Qg + (size_t)(qt * 256 + r) * D_MODEL + d4 * 4);
        Qs[(d4*4+0)*QPITCH + r] = v.x;
        Qs[(d4*4+1)*QPITCH + r] = v.y;
        Qs[(d4*4+2)*QPITCH + r] = v.z;
        Qs[(d4*4+3)*QPITCH + r] = v.w;
    }

    float O[8][8] = {};
    float m8[8], l8[8];
#pragma unroll
    for (int i = 0; i < 8; i++) { m8[i] = -1e30f; l8[i] = 0.0f; }

    int kt0 = (64 * sp) / NSPLIT;
    int kt1 = (64 * (sp + 1)) / NSPLIT;

    for (int kt = kt0; kt < kt1; kt++) {
        __syncthreads();                    // prior Pt/Vs reads done
        // load K transposed + V natural
#pragma unroll
        for (int t = 0; t < 4; t++) {
            int idx = tid + t * 256;
            int r = idx & 63, d4 = idx >> 6;
            float4 kv = *(const float4*)(Kg + (size_t)(kt * 64 + r) * D_MODEL + d4 * 4);
            Ks[(d4*4+0)*KPITCH + r] = kv.x;
            Ks[(d4*4+1)*KPITCH + r] = kv.y;
            Ks[(d4*4+2)*KPITCH + r] = kv.z;
            Ks[(d4*4+3)*KPITCH + r] = kv.w;
            float4 vv = *(const float4*)(Vg + (size_t)(kt * 64 + r) * D_MODEL + d4 * 4);
            *(float4*)(Vs + r * KPITCH + d4 * 4) = vv;
        }
        __syncthreads();

        // S = Q K^T (8x8 per thread)
        float S[8][8] = {};
#pragma unroll 16
        for (int d = 0; d < 64; d++) {
            float4 a0 = *(const float4*)(Qs + d * QPITCH + ty * 8);
            float4 a1 = *(const float4*)(Qs + d * QPITCH + ty * 8 + 4);
            float4 b0 = *(const float4*)(Ks + d * KPITCH + tx * 8);
            float4 b1 = *(const float4*)(Ks + d * KPITCH + tx * 8 + 4);
            float av[8] = {a0.x,a0.y,a0.z,a0.w,a1.x,a1.y,a1.z,a1.w};
            float bv[8] = {b0.x,b0.y,b0.z,b0.w,b1.x,b1.y,b1.z,b1.w};
#pragma unroll
            for (int i = 0; i < 8; i++)
#pragma unroll
                for (int j = 0; j < 8; j++)
                    S[i][j] += av[i] * bv[j];
        }
#pragma unroll
        for (int i = 0; i < 8; i++)
#pragma unroll
            for (int j = 0; j < 8; j++)
                S[i][j] *= ATT_SCALE;

        // online softmax in registers; reduce over tx via shfl (8-lane groups)
#pragma unroll
        for (int i = 0; i < 8; i++) {
            float mx = S[i][0];
#pragma unroll
            for (int j = 1; j < 8; j++) mx = fmaxf(mx, S[i][j]);
            mx = fmaxf(mx, __shfl_xor_sync(0xffffffffu, mx, 1));
            mx = fmaxf(mx, __shfl_xor_sync(0xffffffffu, mx, 2));
            mx = fmaxf(mx, __shfl_xor_sync(0xffffffffu, mx, 4));
            float nm = fmaxf(m8[i], mx);
            float alpha = __expf(m8[i] - nm);
            m8[i] = nm;
            float ps = 0.0f;
#pragma unroll
            for (int j = 0; j < 8; j++) {
                float p = __expf(S[i][j] - nm);
                S[i][j] = p;
                ps += p;
            }
            ps += __shfl_xor_sync(0xffffffffu, ps, 1);
            ps += __shfl_xor_sync(0xffffffffu, ps, 2);
            ps += __shfl_xor_sync(0xffffffffu, ps, 4);
            l8[i] = l8[i] * alpha + ps;
#pragma unroll
            for (int j = 0; j < 8; j++) O[i][j] *= alpha;
        }

        // store P transposed (swizzled float4) : Pt[c][r]
#pragma unroll
        for (int j = 0; j < 8; j++) {
            int c = tx * 8 + j;
            float* base = Pt + c * QPITCH;
#pragma unroll
            for (int q = 0; q < 2; q++) {
                int r4 = ty * 2 + q;
                int p4 = (r4 & ~7) | ((r4 & 7) ^ tx);   // tx == c>>3
                *(float4*)(base + p4 * 4) =
                    make_float4(S[q*4+0][j], S[q*4+1][j], S[q*4+2][j], S[q*4+3][j]);
            }
        }
        __syncthreads();

        // O += P V (8x8 per thread)
#pragma unroll 8
        for (int k = 0; k < 64; k++) {
            int s = k >> 3;
            int r4a = ty * 2, r4b = ty * 2 + 1;
            float4 a0 = *(const float4*)(Pt + k * QPITCH + (((r4a & ~7) | ((r4a & 7) ^ s)) * 4));
            float4 a1 = *(const float4*)(Pt + k * QPITCH + (((r4b & ~7) | ((r4b & 7) ^ s)) * 4));
            float4 b0 = *(const float4*)(Vs + k * KPITCH + tx * 8);
            float4 b1 = *(const float4*)(Vs + k * KPITCH + tx * 8 + 4);
            float av[8] = {a0.x,a0.y,a0.z,a0.w,a1.x,a1.y,a1.z,a1.w};
            float bv[8] = {b0.x,b0.y,b0.z,b0.w,b1.x,b1.y,b1.z,b1.w};
#pragma unroll
            for (int i = 0; i < 8; i++)
#pragma unroll
                for (int j = 0; j < 8; j++)
                    O[i][j] += av[i] * bv[j];
        }
    }

    // write unnormalized partial O + (m, l)
    float* Op = g_opart + ((size_t)sp * SEQ + qt * 256) * D_MODEL + h * DK;
#pragma unroll
    for (int i = 0; i < 8; i++) {
        int r = ty * 8 + i;
        *(float4*)(Op + (size_t)r * D_MODEL + tx * 8) =
            make_float4(O[i][0], O[i][1], O[i][2], O[i][3]);
        *(float4*)(Op + (size_t)r * D_MODEL + tx * 8 + 4) =
            make_float4(O[i][4], O[i][5], O[i][6], O[i][7]);
        if (tx == 0) {
            int gr = qt * 256 + r;
            g_ml[((size_t)sp * NH + h) * SEQ + gr] = m8[i];
            g_ml[(size_t)NSPLIT * NH * SEQ + ((size_t)sp * NH + h) * SEQ + gr] = l8[i];
        }
    }
}

// ---------------- combine split-K partials -----------------------------------
__global__ void __launch_bounds__(256) combine_kernel()
{
    int idx = blockIdx.x * 256 + threadIdx.x;   // over SEQ*192 float4
    int r = idx / 192;
    int c4 = idx - r * 192;
    int h = c4 >> 4;
    const size_t MLO = (size_t)NSPLIT * NH * SEQ;

    float m0 = g_ml[((size_t)0 * NH + h) * SEQ + r];
    float m1 = g_ml[((size_t)1 * NH + h) * SEQ + r];
    float m2 = g_ml[((size_t)2 * NH + h) * SEQ + r];
    float M = fmaxf(m0, fmaxf(m1, m2));
    float w0 = __expf(m0 - M), w1 = __expf(m1 - M), w2 = __expf(m2 - M);
    float l0 = g_ml[MLO + ((size_t)0 * NH + h) * SEQ + r];
    float l1 = g_ml[MLO + ((size_t)1 * NH + h) * SEQ + r];
    float l2 = g_ml[MLO + ((size_t)2 * NH + h) * SEQ + r];
    float inv = 1.0f / (w0 * l0 + w1 * l1 + w2 * l2);

    float4 o0 = *(const float4*)(g_opart + ((size_t)0 * SEQ + r) * D_MODEL + c4 * 4);
    float4 o1 = *(const float4*)(g_opart + ((size_t)1 * SEQ + r) * D_MODEL + c4 * 4);
    float4 o2 = *(const float4*)(g_opart + ((size_t)2 * SEQ + r) * D_MODEL + c4 * 4);
    float4 res;
    res.x = (w0 * o0.x + w1 * o1.x + w2 * o2.x) * inv;
    res.y = (w0 * o0.y + w1 * o1.y + w2 * o2.y) * inv;
    res.z = (w0 * o0.z + w1 * o1.z + w2 * o2.z) * inv;
    res.w = (w0 * o0.w + w1 * o1.w + w2 * o2.w) * inv;
    *(float4*)(g_attn + (size_t)r * D_MODEL + c4 * 4) = res;
}

// ---------------- launch -----------------------------------------------------
extern "C" void kernel_launch(void* const* d_in, const int* in_sizes, int n_in,
                              void* d_out, int out_size) {
    (void)in_sizes; (void)n_in; (void)out_size;
    const float* x       = (const float*)d_in[0];
    const float* wq      = (const float*)d_in[1];
    const float* bq      = (const float*)d_in[2];
    const float* wk      = (const float*)d_in[3];
    const float* bk      = (const float*)d_in[4];
    const float* wv      = (const float*)d_in[5];
    const float* bv      = (const float*)d_in[6];
    const float* wo      = (const float*)d_in[7];
    const float* bo      = (const float*)d_in[8];
    const float* wq_down = (const float*)d_in[9];
    const float* wq_up   = (const float*)d_in[10];
    const float* wk_down = (const float*)d_in[11];
    const float* wk_up   = (const float*)d_in[12];
    const float* wv_down = (const float*)d_in[13];
    const float* wv_up   = (const float*)d_in[14];
    float* out = (float*)d_out;

    float *p_wq, *p_wk, *p_wv, *p_q, *p_k, *p_v, *p_attn;
    cudaGetSymbolAddress((void**)&p_wq, g_wq);
    cudaGetSymbolAddress((void**)&p_wk, g_wk);
    cudaGetSymbolAddress((void**)&p_wv, g_wv);
    cudaGetSymbolAddress((void**)&p_q,  g_q);
    cudaGetSymbolAddress((void**)&p_k,  g_k);
    cudaGetSymbolAddress((void**)&p_v,  g_v);
    cudaGetSymbolAddress((void**)&p_attn, g_attn);

    cudaFuncSetAttribute(flash_attn_split,
                         cudaFuncAttributeMaxDynamicSharedMemorySize, ATT_SMEM_BYTES);

    int fold_blocks = (D_MODEL * D_MODEL + 255) / 256;
    fold_kernel<<<fold_blocks, 256>>>(wq, wq_up, wq_down, p_wq);
    fold_kernel<<<fold_blocks, 256>>>(wk, wk_up, wk_down, p_wk);
    fold_kernel<<<fold_blocks, 256>>>(wv, wv_up, wv_down, p_wv);

    dim3 qkv_grid(SEQ / 128, D_MODEL / 128, 3);
    gemm_qkv<<<qkv_grid, 256>>>(x, p_wq, bq, p_q, p_wk, bk, p_k, p_wv, bv, p_v);

    dim3 agrid(SEQ / 256, NH, NSPLIT);
    flash_attn_split<<<agrid, 256, ATT_SMEM_BYTES>>>();

    combine_kernel<<<(SEQ * (D_MODEL / 4)) / 256, 256>>>();

    dim3 ogrid(SEQ / 128, D_MODEL / 128);
    gemm_one<<<ogrid, 256>>>(p_attn, wo, bo, out);
}

// round 4
// speedup vs baseline: 1.3859x; 1.0817x over previous
#include <cuda_runtime.h>
#include <math.h>

#define D_MODEL 768
#define SEQ     4096
#define NH      12
#define DK      64
#define RANK    8
#define LORA_SCALE 2.0f
#define ATT_SCALE_LOG2 0.18033688f   // (1/8) * log2(e)
#define NSPLIT  3

typedef unsigned long long ull;

// ---- packed f32x2 helpers (Blackwell FFMA2 path, not emitted by ptxas) ------
__device__ __forceinline__ ull ffma2(ull a, ull b, ull c) {
    ull d;
    asm("fma.rn.f32x2 %0, %1, %2, %3;" : "=l"(d) : "l"(a), "l"(b), "l"(c));
    return d;
}
__device__ __forceinline__ ull fmul2(ull a, ull b) {
    ull d;
    asm("mul.rn.f32x2 %0, %1, %2;" : "=l"(d) : "l"(a), "l"(b));
    return d;
}
__device__ __forceinline__ ull pack2(float x) {
    ull d;
    asm("mov.b64 %0, {%1, %1};" : "=l"(d) : "r"(__float_as_uint(x)));
    return d;
}
__device__ __forceinline__ void unpack2(ull v, float& lo, float& hi) {
    unsigned int a, b;
    asm("mov.b64 {%0, %1}, %2;" : "=r"(a), "=r"(b) : "l"(v));
    lo = __uint_as_float(a);
    hi = __uint_as_float(b);
}

// ---------------- scratch (device globals: no allocation allowed) ------------
__device__ float g_wq[D_MODEL * D_MODEL];
__device__ float g_wk[D_MODEL * D_MODEL];
__device__ float g_wv[D_MODEL * D_MODEL];
__device__ float g_q[SEQ * D_MODEL];
__device__ float g_k[SEQ * D_MODEL];
__device__ float g_v[SEQ * D_MODEL];
__device__ float g_attn[SEQ * D_MODEL];
__device__ float g_opart[NSPLIT * SEQ * D_MODEL];
__device__ float g_ml[2 * NSPLIT * NH * SEQ];

// ---------------- fold LoRA into base weight: W_eff = W + 2 * up @ down ------
__global__ void fold_kernel(const float* __restrict__ w,
                            const float* __restrict__ up,
                            const float* __restrict__ dn,
                            float* __restrict__ out) {
    int idx = blockIdx.x * 256 + threadIdx.x;
    if (idx >= D_MODEL * D_MODEL) return;
    int e = idx / D_MODEL, d = idx % D_MODEL;
    float acc = w[idx];
#pragma unroll
    for (int r = 0; r < RANK; r++)
        acc += LORA_SCALE * up[e * RANK + r] * dn[r * D_MODEL + d];
    out[idx] = acc;
}

// ---------------- NT GEMM tile body: Y[M,768] = X[M,768] @ W[768,768]^T + b --
// BM=BN=128, BK=16, 256 threads, 8x8 microtile as 8x4 packed f32x2 pairs.
__device__ __forceinline__ void gemm_tile(const float* __restrict__ X,
                                          const float* __restrict__ W,
                                          const float* __restrict__ bias,
                                          float* __restrict__ Y)
{
    __shared__ __align__(16) float Xs[2][16][132];
    __shared__ __align__(16) float Ws[2][16][132];
    const int K = D_MODEL, N = D_MODEL;
    int tid = threadIdx.x;
    int tx = tid & 15, ty = tid >> 4;
    int m0 = blockIdx.x * 128, n0 = blockIdx.y * 128;
    int lm = tid & 127;
    int lk4 = tid >> 7;

    const float* Xp = X + (size_t)(m0 + lm) * K;
    const float* Wp = W + (size_t)(n0 + lm) * K;

    ull acc2[8][4];
#pragma unroll
    for (int i = 0; i < 8; i++)
#pragma unroll
        for (int j = 0; j < 4; j++) acc2[i][j] = 0ULL;

#pragma unroll
    for (int t = 0; t < 2; t++) {
        int k4 = lk4 + t * 2;
        float4 xv = *(const float4*)(Xp + k4 * 4);
        float4 wv = *(const float4*)(Wp + k4 * 4);
        Xs[0][k4*4+0][lm] = xv.x; Xs[0][k4*4+1][lm] = xv.y;
        Xs[0][k4*4+2][lm] = xv.z; Xs[0][k4*4+3][lm] = xv.w;
        Ws[0][k4*4+0][lm] = wv.x; Ws[0][k4*4+1][lm] = wv.y;
        Ws[0][k4*4+2][lm] = wv.z; Ws[0][k4*4+3][lm] = wv.w;
    }
    __syncthreads();

    const int NIT = K / 16;
    float4 xr[2], wr[2];
    for (int it = 0; it < NIT; it++) {
        int cur = it & 1;
        if (it + 1 < NIT) {
            int k0 = (it + 1) * 16;
#pragma unroll
            for (int t = 0; t < 2; t++) {
                int k4 = lk4 + t * 2;
                xr[t] = *(const float4*)(Xp + k0 + k4 * 4);
                wr[t] = *(const float4*)(Wp + k0 + k4 * 4);
            }
        }
#pragma unroll
        for (int kk = 0; kk < 16; kk++) {
            float4 a0 = *(const float4*)&Xs[cur][kk][ty * 8];
            float4 a1 = *(const float4*)&Xs[cur][kk][ty * 8 + 4];
            ulonglong2 b01 = *(const ulonglong2*)&Ws[cur][kk][tx * 8];
            ulonglong2 b23 = *(const ulonglong2*)&Ws[cur][kk][tx * 8 + 4];
            ull b2[4] = {b01.x, b01.y, b23.x, b23.y};
            float av[8] = {a0.x,a0.y,a0.z,a0.w,a1.x,a1.y,a1.z,a1.w};
#pragma unroll
            for (int i = 0; i < 8; i++) {
                ull av2 = pack2(av[i]);
#pragma unroll
                for (int j = 0; j < 4; j++)
                    acc2[i][j] = ffma2(av2, b2[j], acc2[i][j]);
            }
        }
        if (it + 1 < NIT) {
            int nb = cur ^ 1;
#pragma unroll
            for (int t = 0; t < 2; t++) {
                int k4 = lk4 + t * 2;
                Xs[nb][k4*4+0][lm] = xr[t].x; Xs[nb][k4*4+1][lm] = xr[t].y;
                Xs[nb][k4*4+2][lm] = xr[t].z; Xs[nb][k4*4+3][lm] = xr[t].w;
                Ws[nb][k4*4+0][lm] = wr[t].x; Ws[nb][k4*4+1][lm] = wr[t].y;
                Ws[nb][k4*4+2][lm] = wr[t].z; Ws[nb][k4*4+3][lm] = wr[t].w;
            }
        }
        __syncthreads();
    }

    float bv8[8];
#pragma unroll
    for (int j = 0; j < 8; j++) bv8[j] = bias[n0 + tx * 8 + j];
#pragma unroll
    for (int i = 0; i < 8; i++) {
        float acc[8];
#pragma unroll
        for (int j = 0; j < 4; j++) unpack2(acc2[i][j], acc[2*j], acc[2*j+1]);
        size_t row = (size_t)(m0 + ty * 8 + i);
        float4 o0 = make_float4(acc[0]+bv8[0], acc[1]+bv8[1], acc[2]+bv8[2], acc[3]+bv8[3]);
        float4 o1 = make_float4(acc[4]+bv8[4], acc[5]+bv8[5], acc[6]+bv8[6], acc[7]+bv8[7]);
        *(float4*)(Y + row * N + n0 + tx * 8)     = o0;
        *(float4*)(Y + row * N + n0 + tx * 8 + 4) = o1;
    }
}

__global__ void __launch_bounds__(256, 2) gemm_one(
    const float* __restrict__ X, const float* __restrict__ W,
    const float* __restrict__ b, float* __restrict__ Y) {
    gemm_tile(X, W, b, Y);
}

__global__ void __launch_bounds__(256, 2) gemm_qkv(
    const float* __restrict__ X,
    const float* __restrict__ W0, const float* __restrict__ B0, float* __restrict__ Y0,
    const float* __restrict__ W1, const float* __restrict__ B1, float* __restrict__ Y1,
    const float* __restrict__ W2, const float* __restrict__ B2, float* __restrict__ Y2)
{
    const float* W; const float* B; float* Y;
    if (blockIdx.z == 0)      { W = W0; B = B0; Y = Y0; }
    else if (blockIdx.z == 1) { W = W1; B = B1; Y = Y1; }
    else                      { W = W2; B = B2; Y = Y2; }
    gemm_tile(X, W, B, Y);
}

// ---------------- flash attention: Q-tile 256, K-tile 64, split-K 3 ----------
// 256 threads as 32(ty) x 8(tx). Packed f32x2 in QK^T and PV mainloops.
// Softmax in exp2 domain (scale*log2e folded into logits).
#define QPITCH 260
#define KPITCH 68
#define ATT_SMEM_BYTES ((64*QPITCH + 64*KPITCH + 64*KPITCH + 64*QPITCH) * 4)

__global__ void __launch_bounds__(256, 1) flash_attn_split()
{
    extern __shared__ __align__(16) float smem[];
    float* Qs = smem;                       // [64][260]  (d-major)
    float* Ks = smem + 64 * QPITCH;         // [64][68]   (d-major)
    float* Vs = Ks + 64 * KPITCH;           // [64][68]   (k-major)
    float* Pt = Vs + 64 * KPITCH;           // [64][260]  (k-major, swizzled)

    int tid = threadIdx.x;
    int tx = tid & 7, ty = tid >> 3;
    int qt = blockIdx.x, h = blockIdx.y, sp = blockIdx.z;

    const float* Qg = g_q + h * DK;
    const float* Kg = g_k + h * DK;
    const float* Vg = g_v + h * DK;

#pragma unroll
    for (int t = 0; t < 16; t++) {
        int idx = tid + t * 256;
        int r = idx & 255, d4 = idx >> 8;
        float4 v = *(const float4*)(Qg + (size_t)(qt * 256 + r) * D_MODEL + d4 * 4);
        Qs[(d4*4+0)*QPITCH + r] = v.x;
        Qs[(d4*4+1)*QPITCH + r] = v.y;
        Qs[(d4*4+2)*QPITCH + r] = v.z;
        Qs[(d4*4+3)*QPITCH + r] = v.w;
    }

    ull O2[8][4];
#pragma unroll
    for (int i = 0; i < 8; i++)
#pragma unroll
        for (int j = 0; j < 4; j++) O2[i][j] = 0ULL;
    float m8[8], l8[8];
#pragma unroll
    for (int i = 0; i < 8; i++) { m8[i] = -1e30f; l8[i] = 0.0f; }

    int kt0 = (64 * sp) / NSPLIT;
    int kt1 = (64 * (sp + 1)) / NSPLIT;

    for (int kt = kt0; kt < kt1; kt++) {
        __syncthreads();
#pragma unroll
        for (int t = 0; t < 4; t++) {
            int idx = tid + t * 256;
            int r = idx & 63, d4 = idx >> 6;
            float4 kv = *(const float4*)(Kg + (size_t)(kt * 64 + r) * D_MODEL + d4 * 4);
            Ks[(d4*4+0)*KPITCH + r] = kv.x;
            Ks[(d4*4+1)*KPITCH + r] = kv.y;
            Ks[(d4*4+2)*KPITCH + r] = kv.z;
            Ks[(d4*4+3)*KPITCH + r] = kv.w;
            float4 vv = *(const float4*)(Vg + (size_t)(kt * 64 + r) * D_MODEL + d4 * 4);
            *(float4*)(Vs + r * KPITCH + d4 * 4) = vv;
        }
        __syncthreads();

        // S = Q K^T, packed f32x2
        ull S2[8][4];
#pragma unroll
        for (int i = 0; i < 8; i++)
#pragma unroll
            for (int j = 0; j < 4; j++) S2[i][j] = 0ULL;
#pragma unroll 16
        for (int d = 0; d < 64; d++) {
            float4 a0 = *(const float4*)(Qs + d * QPITCH + ty * 8);
            float4 a1 = *(const float4*)(Qs + d * QPITCH + ty * 8 + 4);
            ulonglong2 b01 = *(const ulonglong2*)(Ks + d * KPITCH + tx * 8);
            ulonglong2 b23 = *(const ulonglong2*)(Ks + d * KPITCH + tx * 8 + 4);
            ull b2[4] = {b01.x, b01.y, b23.x, b23.y};
            float av[8] = {a0.x,a0.y,a0.z,a0.w,a1.x,a1.y,a1.z,a1.w};
#pragma unroll
            for (int i = 0; i < 8; i++) {
                ull av2 = pack2(av[i]);
#pragma unroll
                for (int j = 0; j < 4; j++)
                    S2[i][j] = ffma2(av2, b2[j], S2[i][j]);
            }
        }

        // unpack + scale into exp2 domain
        float S[8][8];
#pragma unroll
        for (int i = 0; i < 8; i++)
#pragma unroll
            for (int j = 0; j < 4; j++) {
                unpack2(S2[i][j], S[i][2*j], S[i][2*j+1]);
                S[i][2*j]   *= ATT_SCALE_LOG2;
                S[i][2*j+1] *= ATT_SCALE_LOG2;
            }

        // online softmax (base-2), tx-group reduction via shfl
#pragma unroll
        for (int i = 0; i < 8; i++) {
            float mx = S[i][0];
#pragma unroll
            for (int j = 1; j < 8; j++) mx = fmaxf(mx, S[i][j]);
            mx = fmaxf(mx, __shfl_xor_sync(0xffffffffu, mx, 1));
            mx = fmaxf(mx, __shfl_xor_sync(0xffffffffu, mx, 2));
            mx = fmaxf(mx, __shfl_xor_sync(0xffffffffu, mx, 4));
            float nm = fmaxf(m8[i], mx);
            float alpha = exp2f(m8[i] - nm);
            m8[i] = nm;
            float ps = 0.0f;
#pragma unroll
            for (int j = 0; j < 8; j++) {
                float p = exp2f(S[i][j] - nm);
                S[i][j] = p;
                ps += p;
            }
            ps += __shfl_xor_sync(0xffffffffu, ps, 1);
            ps += __shfl_xor_sync(0xffffffffu, ps, 2);
            ps += __shfl_xor_sync(0xffffffffu, ps, 4);
            l8[i] = l8[i] * alpha + ps;
            ull al2 = pack2(alpha);
#pragma unroll
            for (int j = 0; j < 4; j++) O2[i][j] = fmul2(O2[i][j], al2);
        }

        // store P transposed (swizzled float4): Pt[c][r]
#pragma unroll
        for (int j = 0; j < 8; j++) {
            int c = tx * 8 + j;
            float* base = Pt + c * QPITCH;
#pragma unroll
            for (int q = 0; q < 2; q++) {
                int r4 = ty * 2 + q;
                int p4 = (r4 & ~7) | ((r4 & 7) ^ tx);
                *(float4*)(base + p4 * 4) =
                    make_float4(S[q*4+0][j], S[q*4+1][j], S[q*4+2][j], S[q*4+3][j]);
            }
        }
        __syncthreads();

        // O += P V, packed f32x2
#pragma unroll 8
        for (int k = 0; k < 64; k++) {
            int s = k >> 3;
            int r4a = ty * 2, r4b = ty * 2 + 1;
            float4 a0 = *(const float4*)(Pt + k * QPITCH + (((r4a & ~7) | ((r4a & 7) ^ s)) * 4));
            float4 a1 = *(const float4*)(Pt + k * QPITCH + (((r4b & ~7) | ((r4b & 7) ^ s)) * 4));
            ulonglong2 b01 = *(const ulonglong2*)(Vs + k * KPITCH + tx * 8);
            ulonglong2 b23 = *(const ulonglong2*)(Vs + k * KPITCH + tx * 8 + 4);
            ull b2[4] = {b01.x, b01.y, b23.x, b23.y};
            float av[8] = {a0.x,a0.y,a0.z,a0.w,a1.x,a1.y,a1.z,a1.w};
#pragma unroll
            for (int i = 0; i < 8; i++) {
                ull av2 = pack2(av[i]);
#pragma unroll
                for (int j = 0; j < 4; j++)
                    O2[i][j] = ffma2(av2, b2[j], O2[i][j]);
            }
        }
    }

    // write unnormalized partial O + (m, l)
    float* Op = g_opart + ((size_t)sp * SEQ + qt * 256) * D_MODEL + h * DK;
#pragma unroll
    for (int i = 0; i < 8; i++) {
        float O[8];
#pragma unroll
        for (int j = 0; j < 4; j++) unpack2(O2[i][j], O[2*j], O[2*j+1]);
        int r = ty * 8 + i;
        *(float4*)(Op + (size_t)r * D_MODEL + tx * 8) =
            make_float4(O[0], O[1], O[2], O[3]);
        *(float4*)(Op + (size_t)r * D_MODEL + tx * 8 + 4) =
            make_float4(O[4], O[5], O[6], O[7]);
        if (tx == 0) {
            int gr = qt * 256 + r;
            g_ml[((size_t)sp * NH + h) * SEQ + gr] = m8[i];
            g_ml[(size_t)NSPLIT * NH * SEQ + ((size_t)sp * NH + h) * SEQ + gr] = l8[i];
        }
    }
}

// ---------------- combine split-K partials (exp2 domain) ---------------------
__global__ void __launch_bounds__(256) combine_kernel()
{
    int idx = blockIdx.x * 256 + threadIdx.x;
    int r = idx / 192;
    int c4 = idx - r * 192;
    int h = c4 >> 4;
    const size_t MLO = (size_t)NSPLIT * NH * SEQ;

    float m0 = g_ml[((size_t)0 * NH + h) * SEQ + r];
    float m1 = g_ml[((size_t)1 * NH + h) * SEQ + r];
    float m2 = g_ml[((size_t)2 * NH + h) * SEQ + r];
    float M = fmaxf(m0, fmaxf(m1, m2));
    float w0 = exp2f(m0 - M), w1 = exp2f(m1 - M), w2 = exp2f(m2 - M);
    float l0 = g_ml[MLO + ((size_t)0 * NH + h) * SEQ + r];
    float l1 = g_ml[MLO + ((size_t)1 * NH + h) * SEQ + r];
    float l2 = g_ml[MLO + ((size_t)2 * NH + h) * SEQ + r];
    float inv = 1.0f / (w0 * l0 + w1 * l1 + w2 * l2);

    float4 o0 = *(const float4*)(g_opart + ((size_t)0 * SEQ + r) * D_MODEL + c4 * 4);
    float4 o1 = *(const float4*)(g_opart + ((size_t)1 * SEQ + r) * D_MODEL + c4 * 4);
    float4 o2 = *(const float4*)(g_opart + ((size_t)2 * SEQ + r) * D_MODEL + c4 * 4);
    float4 res;
    res.x = (w0 * o0.x + w1 * o1.x + w2 * o2.x) * inv;
    res.y = (w0 * o0.y + w1 * o1.y + w2 * o2.y) * inv;
    res.z = (w0 * o0.z + w1 * o1.z + w2 * o2.z) * inv;
    res.w = (w0 * o0.w + w1 * o1.w + w2 * o2.w) * inv;
    *(float4*)(g_attn + (size_t)r * D_MODEL + c4 * 4) = res;
}

// ---------------- launch -----------------------------------------------------
extern "C" void kernel_launch(void* const* d_in, const int* in_sizes, int n_in,
                              void* d_out, int out_size) {
    (void)in_sizes; (void)n_in; (void)out_size;
    const float* x       = (const float*)d_in[0];
    const float* wq      = (const float*)d_in[1];
    const float* bq      = (const float*)d_in[2];
    const float* wk      = (const float*)d_in[3];
    const float* bk      = (const float*)d_in[4];
    const float* wv      = (const float*)d_in[5];
    const float* bv      = (const float*)d_in[6];
    const float* wo      = (const float*)d_in[7];
    const float* bo      = (const float*)d_in[8];
    const float* wq_down = (const float*)d_in[9];
    const float* wq_up   = (const float*)d_in[10];
    const float* wk_down = (const float*)d_in[11];
    const float* wk_up   = (const float*)d_in[12];
    const float* wv_down = (const float*)d_in[13];
    const float* wv_up   = (const float*)d_in[14];
    float* out = (float*)d_out;

    float *p_wq, *p_wk, *p_wv, *p_q, *p_k, *p_v, *p_attn;
    cudaGetSymbolAddress((void**)&p_wq, g_wq);
    cudaGetSymbolAddress((void**)&p_wk, g_wk);
    cudaGetSymbolAddress((void**)&p_wv, g_wv);
    cudaGetSymbolAddress((void**)&p_q,  g_q);
    cudaGetSymbolAddress((void**)&p_k,  g_k);
    cudaGetSymbolAddress((void**)&p_v,  g_v);
    cudaGetSymbolAddress((void**)&p_attn, g_attn);

    cudaFuncSetAttribute(flash_attn_split,
                         cudaFuncAttributeMaxDynamicSharedMemorySize, ATT_SMEM_BYTES);

    int fold_blocks = (D_MODEL * D_MODEL + 255) / 256;
    fold_kernel<<<fold_blocks, 256>>>(wq, wq_up, wq_down, p_wq);
    fold_kernel<<<fold_blocks, 256>>>(wk, wk_up, wk_down, p_wk);
    fold_kernel<<<fold_blocks, 256>>>(wv, wv_up, wv_down, p_wv);

    dim3 qkv_grid(SEQ / 128, D_MODEL / 128, 3);
    gemm_qkv<<<qkv_grid, 256>>>(x, p_wq, bq, p_q, p_wk, bk, p_k, p_wv, bv, p_v);

    dim3 agrid(SEQ / 256, NH, NSPLIT);
    flash_attn_split<<<agrid, 256, ATT_SMEM_BYTES>>>();

    combine_kernel<<<(SEQ * (D_MODEL / 4)) / 256, 256>>>();

    dim3 ogrid(SEQ / 128, D_MODEL / 128);
    gemm_one<<<ogrid, 256>>>(p_attn, wo, bo, out);
}

// round 8
// speedup vs baseline: 2.7906x; 2.0135x over previous
#include <cuda_runtime.h>
#include <cuda_bf16.h>
#include <cstdint>
#include <math.h>

#define D_MODEL 768
#define SEQ     4096
#define NH      12
#define DK      64
#define RANK    8
#define LORA_SCALE 2.0f
#define ATT_QSCALE 0.18033688011f   // 0.125 * log2(e)
#define NSPLIT  3

typedef __nv_bfloat16 bf16;

// ======================= PTX helpers (baseline ISA only) =====================
__device__ __forceinline__ uint32_t s2u(const void* p) {
    uint32_t a;
    asm("{ .reg .u64 t; cvta.to.shared.u64 t, %1; cvt.u32.u64 %0, t; }"
        : "=r"(a) : "l"(p));
    return a;
}
__device__ __forceinline__ void ldsm_x4(uint32_t* r, uint32_t a) {
    asm volatile("ldmatrix.sync.aligned.m8n8.x4.shared.b16 {%0,%1,%2,%3}, [%4];"
        : "=r"(r[0]), "=r"(r[1]), "=r"(r[2]), "=r"(r[3]) : "r"(a));
}
__device__ __forceinline__ void ldsm_x4_t(uint32_t* r, uint32_t a) {
    asm volatile("ldmatrix.sync.aligned.m8n8.x4.trans.shared.b16 {%0,%1,%2,%3}, [%4];"
        : "=r"(r[0]), "=r"(r[1]), "=r"(r[2]), "=r"(r[3]) : "r"(a));
}
// D (f32x4) += A (bf16 m16k16, 4 regs) * B (bf16 k16n8, 2 regs)
__device__ __forceinline__ void mma16816(float* d, const uint32_t* a,
                                         uint32_t b0, uint32_t b1) {
    asm volatile("mma.sync.aligned.m16n8k16.row.col.f32.bf16.bf16.f32 "
        "{%0,%1,%2,%3}, {%4,%5,%6,%7}, {%8,%9}, {%0,%1,%2,%3};"
        : "+f"(d[0]), "+f"(d[1]), "+f"(d[2]), "+f"(d[3])
        : "r"(a[0]), "r"(a[1]), "r"(a[2]), "r"(a[3]), "r"(b0), "r"(b1));
}
// pack two f32 -> bf16x2 (lo = first arg)
__device__ __forceinline__ uint32_t packbf(float lo, float hi) {
    uint32_t d;
    asm("cvt.rn.bf16x2.f32 %0, %1, %2;" : "=r"(d) : "f"(hi), "f"(lo));
    return d;
}
__device__ __forceinline__ float bf_lo(uint32_t u) { return __uint_as_float(u << 16); }
__device__ __forceinline__ float bf_hi(uint32_t u) { return __uint_as_float(u & 0xffff0000u); }

// split two floats into hi/lo bf16x2 packs
__device__ __forceinline__ void split2(float f0, float f1, uint32_t& hp, uint32_t& lp) {
    hp = packbf(f0, f1);
    lp = packbf(f0 - bf_lo(hp), f1 - bf_hi(hp));
}

// ======================= scratch globals =====================================
__device__ float g_wq[D_MODEL * D_MODEL];
__device__ float g_wk[D_MODEL * D_MODEL];
__device__ float g_wv[D_MODEL * D_MODEL];
__device__ float g_q[SEQ * D_MODEL];
__device__ float g_k[SEQ * D_MODEL];
__device__ float g_v[SEQ * D_MODEL];
__device__ float g_attn[SEQ * D_MODEL];
__device__ float g_opart[NSPLIT * SEQ * D_MODEL];
__device__ float g_ml[2 * NSPLIT * NH * SEQ];
__device__ bf16 g_xh[SEQ * D_MODEL],  g_xl[SEQ * D_MODEL];
__device__ bf16 g_ah[SEQ * D_MODEL],  g_al[SEQ * D_MODEL];
__device__ bf16 g_wqh[D_MODEL * D_MODEL], g_wql[D_MODEL * D_MODEL];
__device__ bf16 g_wkh[D_MODEL * D_MODEL], g_wkl[D_MODEL * D_MODEL];
__device__ bf16 g_wvh[D_MODEL * D_MODEL], g_wvl[D_MODEL * D_MODEL];
__device__ bf16 g_woh[D_MODEL * D_MODEL], g_wol[D_MODEL * D_MODEL];

// ======================= small prep kernels ==================================
__global__ void fold_kernel(const float* __restrict__ w,
                            const float* __restrict__ up,
                            const float* __restrict__ dn,
                            float* __restrict__ out) {
    int idx = blockIdx.x * 256 + threadIdx.x;
    if (idx >= D_MODEL * D_MODEL) return;
    int e = idx / D_MODEL, d = idx % D_MODEL;
    float acc = w[idx];
#pragma unroll
    for (int r = 0; r < RANK; r++)
        acc += LORA_SCALE * up[e * RANK + r] * dn[r * D_MODEL + d];
    out[idx] = acc;
}

__global__ void split_kernel(const float* __restrict__ in,
                             bf16* __restrict__ hi, bf16* __restrict__ lo, int n) {
    int i = blockIdx.x * 256 + threadIdx.x;
    if (i >= n) return;
    float v = in[i];
    bf16 h = __float2bfloat16(v);
    hi[i] = h;
    lo[i] = __float2bfloat16(v - __bfloat162float(h));
}

// ======================= HMMA split-bf16 GEMM ================================
// Y[*,768] = (Xh+Xl) @ (Wh+Wl)^T + bias (3-term). CTA tile 128x128, 8 warps,
// each warp a 16-row band x 128 cols (16 ntiles). K chunks of 64 via smem.
#define GP 72                         // smem pitch (bf16 elems), conflict-free ldsm
#define G_TILE (128 * GP)             // bf16 elems per tile
#define GEMM_SMEM_BYTES (4 * G_TILE * 2)

__device__ __forceinline__ void gemm_mma_body(
    const bf16* __restrict__ Xh, const bf16* __restrict__ Xl,
    const bf16* __restrict__ Wh, const bf16* __restrict__ Wl,
    const float* __restrict__ bias, float* __restrict__ Y)
{
    extern __shared__ __align__(16) char smem[];
    bf16* sm = (bf16*)smem;
    uint32_t base = s2u(smem);
    int tid = threadIdx.x;
    int wid = tid >> 5, lane = tid & 31;
    int m0 = blockIdx.x * 128, n0 = blockIdx.y * 128;

    float acc[16][4];
#pragma unroll
    for (int a = 0; a < 16; a++)
#pragma unroll
        for (int b = 0; b < 4; b++) acc[a][b] = 0.0f;

    // ldmatrix lane address components
    int li = lane >> 3, lj = lane & 7;
    int arow  = wid * 16 + ((li & 1) << 3) + lj;   // A: row within 16-band
    int acolo = (li >> 1) << 3;
    int brow  = ((li >> 1) << 3) + lj;             // B: row (n), add ntile*16
    int bcolo = (li & 1) << 3;

    // loader assignment: tile lt (0=Xh,1=Xl,2=Wh,3=Wl), 64 threads each
    int lt = tid >> 6, lidx = tid & 63;
    const bf16* srcs[4] = {Xh, Xl, Wh, Wl};
    int rb = (lt < 2) ? m0 : n0;
    const bf16* gsrc = srcs[lt] + (size_t)rb * D_MODEL;
    bf16* dp = sm + lt * G_TILE;

    for (int c = 0; c < 12; c++) {
        __syncthreads();
        int k0 = c * 64;
#pragma unroll
        for (int t = 0; t < 16; t++) {
            int idx = lidx + t * 64;
            int row = idx >> 3, c8 = idx & 7;
            uint4 v = *(const uint4*)(gsrc + (size_t)row * D_MODEL + k0 + c8 * 8);
            *(uint4*)(dp + row * GP + c8 * 8) = v;
        }
        __syncthreads();
#pragma unroll
        for (int k4 = 0; k4 < 4; k4++) {
            uint32_t ah[4], al[4];
            ldsm_x4(ah, base + 2u * (0 * G_TILE + arow * GP + k4 * 16 + acolo));
            ldsm_x4(al, base + 2u * (1 * G_TILE + arow * GP + k4 * 16 + acolo));
#pragma unroll
            for (int n2 = 0; n2 < 8; n2++) {
                uint32_t bh[4], bl[4];
                ldsm_x4(bh, base + 2u * (2 * G_TILE + (n2 * 16 + brow) * GP + k4 * 16 + bcolo));
                ldsm_x4(bl, base + 2u * (3 * G_TILE + (n2 * 16 + brow) * GP + k4 * 16 + bcolo));
                mma16816(acc[2*n2],   ah, bh[0], bh[1]);
                mma16816(acc[2*n2],   ah, bl[0], bl[1]);
                mma16816(acc[2*n2],   al, bh[0], bh[1]);
                mma16816(acc[2*n2+1], ah, bh[2], bh[3]);
                mma16816(acc[2*n2+1], ah, bl[2], bl[3]);
                mma16816(acc[2*n2+1], al, bh[2], bh[3]);
            }
        }
    }

    int r0 = m0 + wid * 16 + (lane >> 2);
    int cb = n0 + (lane & 3) * 2;
#pragma unroll
    for (int nt = 0; nt < 16; nt++) {
        int col = cb + nt * 8;
        float b0 = bias[col], b1 = bias[col + 1];
        float2 oA = make_float2(acc[nt][0] + b0, acc[nt][1] + b1);
        float2 oB = make_float2(acc[nt][2] + b0, acc[nt][3] + b1);
        *(float2*)(Y + (size_t)r0 * D_MODEL + col)       = oA;
        *(float2*)(Y + (size_t)(r0 + 8) * D_MODEL + col) = oB;
    }
}

__global__ void __launch_bounds__(256, 2) gemm_mma_qkv(
    const bf16* Xh, const bf16* Xl,
    const bf16* Wqh, const bf16* Wql, const float* Bq, float* Yq,
    const bf16* Wkh, const bf16* Wkl, const float* Bk, float* Yk,
    const bf16* Wvh, const bf16* Wvl, const float* Bv, float* Yv)
{
    if (blockIdx.z == 0)      gemm_mma_body(Xh, Xl, Wqh, Wql, Bq, Yq);
    else if (blockIdx.z == 1) gemm_mma_body(Xh, Xl, Wkh, Wkl, Bk, Yk);
    else                      gemm_mma_body(Xh, Xl, Wvh, Wvl, Bv, Yv);
}

__global__ void __launch_bounds__(256, 2) gemm_mma_one(
    const bf16* Xh, const bf16* Xl,
    const bf16* Wh, const bf16* Wl, const float* B, float* Y)
{
    gemm_mma_body(Xh, Xl, Wh, Wl, B, Y);
}

// ======================= HMMA flash attention ================================
// Q tile 128 x 64, 8 warps (16 q-rows each). Key chunks of 64, split-K 3.
// S and O live in m16n8 acc frags; P converted in-register to A frags.
// Q pre-scaled by 0.125*log2(e) -> softmax in exp2 domain.
#define AP 72
#define A_QH 0
#define A_QL (128 * AP)
#define A_KH (2 * 128 * AP)
#define A_KL (A_KH + 64 * AP)
#define A_VH (A_KL + 64 * AP)
#define A_VL (A_VH + 64 * AP)
#define ATT_SMEM_BYTES ((2 * 128 * AP + 4 * 64 * AP) * 2)

__global__ void __launch_bounds__(256) flash_attn_mma()
{
    extern __shared__ __align__(16) char smem[];
    bf16* sm = (bf16*)smem;
    uint32_t base = s2u(smem);
    int tid = threadIdx.x;
    int wid = tid >> 5, lane = tid & 31;
    int qt = blockIdx.x, h = blockIdx.y, sp = blockIdx.z;

    int li = lane >> 3, lj = lane & 7;
    int arow  = wid * 16 + ((li & 1) << 3) + lj;
    int acolo = (li >> 1) << 3;
    int brow  = ((li >> 1) << 3) + lj;     // K frags: row=key
    int bcolo = (li & 1) << 3;
    int vrow  = ((li & 1) << 3) + lj;      // V frags (trans): row=key, add ktile*16
    int vcolo = (li >> 1) << 3;

    // ---- load Q (128x64 f32), scale, split to smem ----
    const float* Qg = g_q + (size_t)(qt * 128) * D_MODEL + h * DK;
#pragma unroll
    for (int t = 0; t < 8; t++) {
        int idx = tid + t * 256;          // 2048 float4
        int row = idx >> 4, c4 = idx & 15;
        float4 v = *(const float4*)(Qg + (size_t)row * D_MODEL + c4 * 4);
        v.x *= ATT_QSCALE; v.y *= ATT_QSCALE; v.z *= ATT_QSCALE; v.w *= ATT_QSCALE;
        uint32_t h0, l0, h1, l1;
        split2(v.x, v.y, h0, l0);
        split2(v.z, v.w, h1, l1);
        *(uint2*)(sm + A_QH + row * AP + c4 * 4) = make_uint2(h0, h1);
        *(uint2*)(sm + A_QL + row * AP + c4 * 4) = make_uint2(l0, l1);
    }
    __syncthreads();

    // persistent Q fragments
    uint32_t qh[4][4], ql[4][4];
#pragma unroll
    for (int k4 = 0; k4 < 4; k4++) {
        ldsm_x4(qh[k4], base + 2u * (A_QH + arow * AP + k4 * 16 + acolo));
        ldsm_x4(ql[k4], base + 2u * (A_QL + arow * AP + k4 * 16 + acolo));
    }

    float Oa[8][4];
#pragma unroll
    for (int a = 0; a < 8; a++)
#pragma unroll
        for (int b = 0; b < 4; b++) Oa[a][b] = 0.0f;
    float mA = -1e30f, mB = -1e30f, lA = 0.0f, lB = 0.0f;

    int kt0 = (64 * sp) / NSPLIT;
    int kt1 = (64 * (sp + 1)) / NSPLIT;

    const float* Kg = g_k + h * DK;
    const float* Vg = g_v + h * DK;

    for (int kt = kt0; kt < kt1; kt++) {
        __syncthreads();
        // load+split K,V chunk (64x64 each)
#pragma unroll
        for (int t = 0; t < 4; t++) {
            int idx = tid + t * 256;      // 1024 float4 per tensor
            int row = idx >> 4, c4 = idx & 15;
            size_t goff = (size_t)(kt * 64 + row) * D_MODEL + c4 * 4;
            float4 kv = *(const float4*)(Kg + goff);
            uint32_t h0, l0, h1, l1;
            split2(kv.x, kv.y, h0, l0);
            split2(kv.z, kv.w, h1, l1);
            *(uint2*)(sm + A_KH + row * AP + c4 * 4) = make_uint2(h0, h1);
            *(uint2*)(sm + A_KL + row * AP + c4 * 4) = make_uint2(l0, l1);
            float4 vv = *(const float4*)(Vg + goff);
            split2(vv.x, vv.y, h0, l0);
            split2(vv.z, vv.w, h1, l1);
            *(uint2*)(sm + A_VH + row * AP + c4 * 4) = make_uint2(h0, h1);
            *(uint2*)(sm + A_VL + row * AP + c4 * 4) = make_uint2(l0, l1);
        }
        __syncthreads();

        // ---- S = Q K^T (3-term split) ----
        float S[8][4];
#pragma unroll
        for (int a = 0; a < 8; a++)
#pragma unroll
            for (int b = 0; b < 4; b++) S[a][b] = 0.0f;
#pragma unroll
        for (int k4 = 0; k4 < 4; k4++) {
#pragma unroll
            for (int n2 = 0; n2 < 4; n2++) {
                uint32_t bh[4], bl[4];
                ldsm_x4(bh, base + 2u * (A_KH + (n2 * 16 + brow) * AP + k4 * 16 + bcolo));
                ldsm_x4(bl, base + 2u * (A_KL + (n2 * 16 + brow) * AP + k4 * 16 + bcolo));
                mma16816(S[2*n2],   qh[k4], bh[0], bh[1]);
                mma16816(S[2*n2],   qh[k4], bl[0], bl[1]);
                mma16816(S[2*n2],   ql[k4], bh[0], bh[1]);
                mma16816(S[2*n2+1], qh[k4], bh[2], bh[3]);
                mma16816(S[2*n2+1], qh[k4], bl[2], bl[3]);
                mma16816(S[2*n2+1], ql[k4], bh[2], bh[3]);
            }
        }

        // ---- online softmax (rows lane>>2 and +8; quad reduction) ----
        float mxA = -1e30f, mxB = -1e30f;
#pragma unroll
        for (int nt = 0; nt < 8; nt++) {
            mxA = fmaxf(mxA, fmaxf(S[nt][0], S[nt][1]));
            mxB = fmaxf(mxB, fmaxf(S[nt][2], S[nt][3]));
        }
        mxA = fmaxf(mxA, __shfl_xor_sync(0xffffffffu, mxA, 1));
        mxA = fmaxf(mxA, __shfl_xor_sync(0xffffffffu, mxA, 2));
        mxB = fmaxf(mxB, __shfl_xor_sync(0xffffffffu, mxB, 1));
        mxB = fmaxf(mxB, __shfl_xor_sync(0xffffffffu, mxB, 2));
        float nmA = fmaxf(mA, mxA), nmB = fmaxf(mB, mxB);
        float aA = exp2f(mA - nmA), aB = exp2f(mB - nmB);
        mA = nmA; mB = nmB;
        float sA = 0.0f, sB = 0.0f;
#pragma unroll
        for (int nt = 0; nt < 8; nt++) {
            S[nt][0] = exp2f(S[nt][0] - nmA); sA += S[nt][0];
            S[nt][1] = exp2f(S[nt][1] - nmA); sA += S[nt][1];
            S[nt][2] = exp2f(S[nt][2] - nmB); sB += S[nt][2];
            S[nt][3] = exp2f(S[nt][3] - nmB); sB += S[nt][3];
        }
        sA += __shfl_xor_sync(0xffffffffu, sA, 1);
        sA += __shfl_xor_sync(0xffffffffu, sA, 2);
        sB += __shfl_xor_sync(0xffffffffu, sB, 1);
        sB += __shfl_xor_sync(0xffffffffu, sB, 2);
        lA = lA * aA + sA;
        lB = lB * aB + sB;
#pragma unroll
        for (int nt = 0; nt < 8; nt++) {
            Oa[nt][0] *= aA; Oa[nt][1] *= aA;
            Oa[nt][2] *= aB; Oa[nt][3] *= aB;
        }

        // ---- P acc-frags -> A-frags (hi/lo), in registers ----
        uint32_t ph[4][4], pl[4][4];
#pragma unroll
        for (int t = 0; t < 4; t++) {
            split2(S[2*t][0],   S[2*t][1],   ph[t][0], pl[t][0]);
            split2(S[2*t][2],   S[2*t][3],   ph[t][1], pl[t][1]);
            split2(S[2*t+1][0], S[2*t+1][1], ph[t][2], pl[t][2]);
            split2(S[2*t+1][2], S[2*t+1][3], ph[t][3], pl[t][3]);
        }

        // ---- O += P V (3-term split) ----
#pragma unroll
        for (int t = 0; t < 4; t++) {
#pragma unroll
            for (int n2 = 0; n2 < 4; n2++) {
                uint32_t bh[4], bl[4];
                ldsm_x4_t(bh, base + 2u * (A_VH + (t * 16 + vrow) * AP + n2 * 16 + vcolo));
                ldsm_x4_t(bl, base + 2u * (A_VL + (t * 16 + vrow) * AP + n2 * 16 + vcolo));
                mma16816(Oa[2*n2],   ph[t], bh[0], bh[1]);
                mma16816(Oa[2*n2],   ph[t], bl[0], bl[1]);
                mma16816(Oa[2*n2],   pl[t], bh[0], bh[1]);
                mma16816(Oa[2*n2+1], ph[t], bh[2], bh[3]);
                mma16816(Oa[2*n2+1], ph[t], bl[2], bl[3]);
                mma16816(Oa[2*n2+1], pl[t], bh[2], bh[3]);
            }
        }
    }

    // ---- write unnormalized partial O + (m, l) ----
    int rA = qt * 128 + wid * 16 + (lane >> 2);
    int rB = rA + 8;
    int cb = h * DK + (lane & 3) * 2;
    float* Op = g_opart + (size_t)sp * SEQ * D_MODEL;
#pragma unroll
    for (int nt = 0; nt < 8; nt++) {
        int col = cb + nt * 8;
        *(float2*)(Op + (size_t)rA * D_MODEL + col) = make_float2(Oa[nt][0], Oa[nt][1]);
        *(float2*)(Op + (size_t)rB * D_MODEL + col) = make_float2(Oa[nt][2], Oa[nt][3]);
    }
    if ((lane & 3) == 0) {
        const size_t MLO = (size_t)NSPLIT * NH * SEQ;
        size_t mb = ((size_t)sp * NH + h) * SEQ;
        g_ml[mb + rA] = mA;
        g_ml[mb + rB] = mB;
        g_ml[MLO + mb + rA] = lA;
        g_ml[MLO + mb + rB] = lB;
    }
}

// ======================= combine split-K partials ============================
__global__ void __launch_bounds__(256) combine_kernel()
{
    int idx = blockIdx.x * 256 + threadIdx.x;
    int r = idx / 192;
    int c4 = idx - r * 192;
    int h = c4 >> 4;
    const size_t MLO = (size_t)NSPLIT * NH * SEQ;

    float m0 = g_ml[((size_t)0 * NH + h) * SEQ + r];
    float m1 = g_ml[((size_t)1 * NH + h) * SEQ + r];
    float m2 = g_ml[((size_t)2 * NH + h) * SEQ + r];
    float M = fmaxf(m0, fmaxf(m1, m2));
    float w0 = exp2f(m0 - M), w1 = exp2f(m1 - M), w2 = exp2f(m2 - M);
    float l0 = g_ml[MLO + ((size_t)0 * NH + h) * SEQ + r];
    float l1 = g_ml[MLO + ((size_t)1 * NH + h) * SEQ + r];
    float l2 = g_ml[MLO + ((size_t)2 * NH + h) * SEQ + r];
    float inv = 1.0f / (w0 * l0 + w1 * l1 + w2 * l2);

    float4 o0 = *(const float4*)(g_opart + ((size_t)0 * SEQ + r) * D_MODEL + c4 * 4);
    float4 o1 = *(const float4*)(g_opart + ((size_t)1 * SEQ + r) * D_MODEL + c4 * 4);
    float4 o2 = *(const float4*)(g_opart + ((size_t)2 * SEQ + r) * D_MODEL + c4 * 4);
    float4 res;
    res.x = (w0 * o0.x + w1 * o1.x + w2 * o2.x) * inv;
    res.y = (w0 * o0.y + w1 * o1.y + w2 * o2.y) * inv;
    res.z = (w0 * o0.z + w1 * o1.z + w2 * o2.z) * inv;
    res.w = (w0 * o0.w + w1 * o1.w + w2 * o2.w) * inv;
    *(float4*)(g_attn + (size_t)r * D_MODEL + c4 * 4) = res;
}

// ======================= launch ==============================================
extern "C" void kernel_launch(void* const* d_in, const int* in_sizes, int n_in,
                              void* d_out, int out_size) {
    (void)in_sizes; (void)n_in; (void)out_size;
    const float* x       = (const float*)d_in[0];
    const float* wq      = (const float*)d_in[1];
    const float* bq      = (const float*)d_in[2];
    const float* wk      = (const float*)d_in[3];
    const float* bk      = (const float*)d_in[4];
    const float* wv      = (const float*)d_in[5];
    const float* bv      = (const float*)d_in[6];
    const float* wo      = (const float*)d_in[7];
    const float* bo      = (const float*)d_in[8];
    const float* wq_down = (const float*)d_in[9];
    const float* wq_up   = (const float*)d_in[10];
    const float* wk_down = (const float*)d_in[11];
    const float* wk_up   = (const float*)d_in[12];
    const float* wv_down = (const float*)d_in[13];
    const float* wv_up   = (const float*)d_in[14];
    float* out = (float*)d_out;

    float *p_wq, *p_wk, *p_wv, *p_q, *p_k, *p_v, *p_attn;
    cudaGetSymbolAddress((void**)&p_wq, g_wq);
    cudaGetSymbolAddress((void**)&p_wk, g_wk);
    cudaGetSymbolAddress((void**)&p_wv, g_wv);
    cudaGetSymbolAddress((void**)&p_q,  g_q);
    cudaGetSymbolAddress((void**)&p_k,  g_k);
    cudaGetSymbolAddress((void**)&p_v,  g_v);
    cudaGetSymbolAddress((void**)&p_attn, g_attn);

    bf16 *p_xh, *p_xl, *p_ah, *p_al;
    bf16 *p_wqh, *p_wql, *p_wkh, *p_wkl, *p_wvh, *p_wvl, *p_woh, *p_wol;
    cudaGetSymbolAddress((void**)&p_xh, g_xh);
    cudaGetSymbolAddress((void**)&p_xl, g_xl);
    cudaGetSymbolAddress((void**)&p_ah, g_ah);
    cudaGetSymbolAddress((void**)&p_al, g_al);
    cudaGetSymbolAddress((void**)&p_wqh, g_wqh);
    cudaGetSymbolAddress((void**)&p_wql, g_wql);
    cudaGetSymbolAddress((void**)&p_wkh, g_wkh);
    cudaGetSymbolAddress((void**)&p_wkl, g_wkl);
    cudaGetSymbolAddress((void**)&p_wvh, g_wvh);
    cudaGetSymbolAddress((void**)&p_wvl, g_wvl);
    cudaGetSymbolAddress((void**)&p_woh, g_woh);
    cudaGetSymbolAddress((void**)&p_wol, g_wol);

    cudaFuncSetAttribute(flash_attn_mma,
                         cudaFuncAttributeMaxDynamicSharedMemorySize, ATT_SMEM_BYTES);
    cudaFuncSetAttribute(gemm_mma_qkv,
                         cudaFuncAttributeMaxDynamicSharedMemorySize, GEMM_SMEM_BYTES);
    cudaFuncSetAttribute(gemm_mma_one,
                         cudaFuncAttributeMaxDynamicSharedMemorySize, GEMM_SMEM_BYTES);

    const int NW = D_MODEL * D_MODEL;
    const int NX = SEQ * D_MODEL;
    int fold_blocks = (NW + 255) / 256;

    fold_kernel<<<fold_blocks, 256>>>(wq, wq_up, wq_down, p_wq);
    fold_kernel<<<fold_blocks, 256>>>(wk, wk_up, wk_down, p_wk);
    fold_kernel<<<fold_blocks, 256>>>(wv, wv_up, wv_down, p_wv);

    split_kernel<<<(NX + 255) / 256, 256>>>(x,    p_xh,  p_xl,  NX);
    split_kernel<<<fold_blocks, 256>>>(p_wq, p_wqh, p_wql, NW);
    split_kernel<<<fold_blocks, 256>>>(p_wk, p_wkh, p_wkl, NW);
    split_kernel<<<fold_blocks, 256>>>(p_wv, p_wvh, p_wvl, NW);
    split_kernel<<<fold_blocks, 256>>>(wo,   p_woh, p_wol, NW);

    dim3 qkv_grid(SEQ / 128, D_MODEL / 128, 3);
    gemm_mma_qkv<<<qkv_grid, 256, GEMM_SMEM_BYTES>>>(
        p_xh, p_xl,
        p_wqh, p_wql, bq, p_q,
        p_wkh, p_wkl, bk, p_k,
        p_wvh, p_wvl, bv, p_v);

    dim3 agrid(SEQ / 128, NH, NSPLIT);
    flash_attn_mma<<<agrid, 256, ATT_SMEM_BYTES>>>();

    combine_kernel<<<(SEQ * (D_MODEL / 4)) / 256, 256>>>();

    split_kernel<<<(NX + 255) / 256, 256>>>(p_attn, p_ah, p_al, NX);

    dim3 ogrid(SEQ / 128, D_MODEL / 128);
    gemm_mma_one<<<ogrid, 256, GEMM_SMEM_BYTES>>>(p_ah, p_al, p_woh, p_wol, bo, out);
}